// round 5
// baseline (speedup 1.0000x reference)
#include <cuda_runtime.h>
#include <cstdint>
#include <cstddef>

#define BATCH   16384
#define DIM     64
#define NSTEPS  100
#define BPC     8                 // samples per CTA
#define TPB     512               // BPC * DIM threads
#define NPAIRS  2016              // upper-triangle pairs of 64x64
#define NPAD    2048              // padded pair count = TPB * 4
#define MROWF   68                // padded M row length in floats (conflict-free LDS.128)
#define MSAMP   (DIM * MROWF)     // floats per per-sample M matrix = 4352
#define NGROUP  (BATCH / BPC)     // 2048 CTAs

typedef unsigned long long ull;

__device__ int g_idx[BATCH];
__device__ int g_perm[BATCH];
__device__ int g_pairs[NPAD];
__device__ __align__(16) float g_Gt[DIM * NPAD];   // [k][pair]; dummy pairs hold 0

// ---------------- packed f32x2 helpers (sm_103a) ----------------
__device__ __forceinline__ ull pack2(float x, float y) {
    ull r; asm("mov.b64 %0, {%1, %2};" : "=l"(r) : "f"(x), "f"(y)); return r;
}
__device__ __forceinline__ void unpack2(ull v, float& x, float& y) {
    asm("mov.b64 {%0, %1}, %2;" : "=f"(x), "=f"(y) : "l"(v));
}
__device__ __forceinline__ ull ffma2(ull a, ull b, ull c) {
    ull d; asm("fma.rn.f32x2 %0, %1, %2, %3;" : "=l"(d) : "l"(a), "l"(b), "l"(c));
    return d;
}

// ---------------- kernel A: idx + descending counting sort + pair table ----------------
__global__ void prep_kernel(const float* __restrict__ t) {
    __shared__ int hist[NSTEPS];
    __shared__ int off[NSTEPS];
    const int tid = threadIdx.x;
    if (tid < NSTEPS) hist[tid] = 0;
    __syncthreads();
    for (int b = tid; b < BATCH; b += blockDim.x) {
        int ix = (int)truncf(100.0f * t[b]);      // trunc(n*t/T), T=1
        ix = min(max(ix, 0), NSTEPS - 1);
        g_idx[b] = ix;
        atomicAdd(&hist[ix], 1);
    }
    if (tid == 0) {                               // pair table (i<j), pad with (0,0)
        int p = 0;
        for (int i = 0; i < DIM; ++i)
            for (int j = i + 1; j < DIM; ++j)
                g_pairs[p++] = (i << 8) | j;
        for (; p < NPAD; ++p) g_pairs[p] = 0;
    }
    __syncthreads();
    if (tid == 0) {                               // descending bins: long jobs first
        int run = 0;
        for (int bin = NSTEPS - 1; bin >= 0; --bin) { off[bin] = run; run += hist[bin]; }
    }
    __syncthreads();
    for (int b = tid; b < BATCH; b += blockDim.x) {
        int pos = atomicAdd(&off[g_idx[b]], 1);   // within-bin order irrelevant to output
        g_perm[pos] = b;
    }
}

// ---------------- kernel B: build Gt[k][pair] ----------------
__global__ void gt_kernel(const float* __restrict__ G) {
    int idx = blockIdx.x * blockDim.x + threadIdx.x;   // DIM * NPAD total
    if (idx >= DIM * NPAD) return;
    const int k = idx >> 11;            // / NPAD
    const int p = idx & (NPAD - 1);
    float v = 0.0f;
    if (p < NPAIRS) {
        int pr = g_pairs[p];
        int i = pr >> 8, j = pr & 255;
        v = G[(i * DIM + j) * DIM + k];
    }
    g_Gt[idx] = v;
}

// ---------------- 64-element dot: packed fma, conflict-free LDS.128 ----------------
__device__ __forceinline__ float dot64(const ulonglong2* __restrict__ M8,
                                       const ulonglong2* __restrict__ V8) {
    ull a0 = 0ull, a1 = 0ull;
    #pragma unroll
    for (int q = 0; q < 16; ++q) {
        ulonglong2 m = M8[q];
        ulonglong2 v = V8[q];          // broadcast (all lanes of a b-group share address)
        a0 = ffma2(m.x, v.x, a0);
        a1 = ffma2(m.y, v.y, a1);
    }
    float x0, x1, z0, z1;
    unpack2(a0, x0, x1);
    unpack2(a1, z0, z1);
    return (x0 + x1) + (z0 + z1);
}

// ---------------- main integration kernel ----------------
__global__ void __launch_bounds__(TPB, 1)
sde_kernel(const float* __restrict__ y0,
           const float* __restrict__ dW,
           float* __restrict__ out)
{
    extern __shared__ __align__(16) float smem[];
    float* Msm  = smem;                          // [BPC][64][MROWF]
    float* vbuf = smem + BPC * MSAMP;            // ping-pong [2][TPB]
    float* dwT  = vbuf + 2 * TPB;                // [k][BPC]

    const int tid = threadIdx.x;
    const int b   = tid >> 6;
    const int i   = tid & 63;

    const int sb    = g_perm[blockIdx.x * BPC + b];
    const int myidx = g_idx[sb];
    // perm is sorted descending by idx -> first sample of the group has the max
    const int smax  = g_idx[g_perm[blockIdx.x * BPC]];

    // pair assignments for this thread (4 pairs, contiguous)
    int up_off[4], lo_off[4];
    #pragma unroll
    for (int pp = 0; pp < 4; ++pp) {
        int pr = g_pairs[tid * 4 + pp];
        int ii = pr >> 8, jj = pr & 255;
        up_off[pp] = ii * MROWF + jj;
        lo_off[pp] = jj * MROWF + ii;
    }
    const bool wr = (tid * 4 < NPAIRS);          // threads >= 504 hold only dummy pairs

    Msm[b * MSAMP + i * MROWF + i] = 0.0f;       // diagonal is exactly 0; set once

    float yr   = y0[sb * DIM + i];
    float r_dw = dW[(size_t)sb * DIM + i];       // step 0 increment (prefetched)

    const float4* Gp = reinterpret_cast<const float4*>(g_Gt) + tid;    // Gp[k*512]
    const ulonglong2* Mr = reinterpret_cast<const ulonglong2*>(Msm + b * MSAMP + i * MROWF);
    const ulonglong2* V0 = reinterpret_cast<const ulonglong2*>(vbuf + b * DIM);
    const ulonglong2* V1 = reinterpret_cast<const ulonglong2*>(vbuf + TPB + b * DIM);
    float* Mb = Msm;                              // base; sample offset applied via q*MSAMP

    for (int s = 0; s <= smax; ++s) {
        dwT[i * BPC + b] = r_dw;                  // stage dw_s transposed [k][b]
        vbuf[tid] = yr;                           // v0 = y
        __syncthreads();                          // (A) dwT, v0 visible; prev-step M reads done

        if (s < smax)                             // prefetch next step's dW (hidden by compute)
            r_dw = dW[((size_t)(s + 1) * BATCH + sb) * DIM + i];

        // ---- M formation: acc[pair][sample-pair] over k, packed f32x2 ----
        ull acc[4][4];
        #pragma unroll
        for (int pp = 0; pp < 4; ++pp)
            #pragma unroll
            for (int q = 0; q < 4; ++q) acc[pp][q] = 0ull;

        #pragma unroll 4
        for (int k = 0; k < DIM; ++k) {
            float4 gq = Gp[k * 512];              // coalesced L2-resident stream
            const ulonglong2* wp = reinterpret_cast<const ulonglong2*>(dwT + k * BPC);
            ulonglong2 wA = wp[0];                // samples (b0,b1),(b2,b3)
            ulonglong2 wB = wp[1];                // samples (b4,b5),(b6,b7)
            float gv0 = gq.x, gv1 = gq.y, gv2 = gq.z, gv3 = gq.w;
            ull s0 = pack2(gv0, gv0), s1 = pack2(gv1, gv1);
            ull s2 = pack2(gv2, gv2), s3 = pack2(gv3, gv3);
            acc[0][0] = ffma2(s0, wA.x, acc[0][0]); acc[0][1] = ffma2(s0, wA.y, acc[0][1]);
            acc[0][2] = ffma2(s0, wB.x, acc[0][2]); acc[0][3] = ffma2(s0, wB.y, acc[0][3]);
            acc[1][0] = ffma2(s1, wA.x, acc[1][0]); acc[1][1] = ffma2(s1, wA.y, acc[1][1]);
            acc[1][2] = ffma2(s1, wB.x, acc[1][2]); acc[1][3] = ffma2(s1, wB.y, acc[1][3]);
            acc[2][0] = ffma2(s2, wA.x, acc[2][0]); acc[2][1] = ffma2(s2, wA.y, acc[2][1]);
            acc[2][2] = ffma2(s2, wB.x, acc[2][2]); acc[2][3] = ffma2(s2, wB.y, acc[2][3]);
            acc[3][0] = ffma2(s3, wA.x, acc[3][0]); acc[3][1] = ffma2(s3, wA.y, acc[3][1]);
            acc[3][2] = ffma2(s3, wB.x, acc[3][2]); acc[3][3] = ffma2(s3, wB.y, acc[3][3]);
        }

        if (wr) {                                 // write both triangles (skew is exact)
            #pragma unroll
            for (int pp = 0; pp < 4; ++pp) {
                float* up = Mb + up_off[pp];
                float* lo = Mb + lo_off[pp];
                #pragma unroll
                for (int q = 0; q < 4; ++q) {
                    float va, vb;
                    unpack2(acc[pp][q], va, vb);
                    up[(2 * q + 0) * MSAMP] =  va;  lo[(2 * q + 0) * MSAMP] = -va;
                    up[(2 * q + 1) * MSAMP] =  vb;  lo[(2 * q + 1) * MSAMP] = -vb;
                }
            }
        }
        __syncthreads();                          // (B) M complete

        // ---- RK4 stages (drift is exactly zero; increment = M v) ----
        float u1 = dot64(Mr, V0);
        vbuf[TPB + tid] = yr + 0.5f * u1;
        __syncthreads();                          // (C)
        float u2 = dot64(Mr, V1);
        vbuf[tid] = yr + 0.5f * u2;
        __syncthreads();                          // (D)
        float u3 = dot64(Mr, V0);
        vbuf[TPB + tid] = yr + u3;
        __syncthreads();                          // (E)
        float u4 = dot64(Mr, V1);
        yr += (u1 + 2.0f * u2 + 2.0f * u3 + u4) / 6.0f;

        if (s == myidx) out[sb * DIM + i] = yr;   // fused ys[idx_b] gather
        // loop-top (A) barrier covers all WAR hazards for the next step
    }
}

// ---------------- launch ----------------
extern "C" void kernel_launch(void* const* d_in, const int* in_sizes, int n_in,
                              void* d_out, int out_size) {
    const float* y0 = nullptr;
    const float* t  = nullptr;
    const float* G  = nullptr;
    const float* dW = nullptr;
    for (int k = 0; k < n_in; ++k) {              // robust size-based remap
        const float* p = (const float*)d_in[k];
        long sz = in_sizes[k];
        if      (sz == BATCH)                      t  = p;
        else if (sz == BATCH * DIM)                y0 = p;
        else if (sz == DIM * DIM * DIM)            G  = p;
        else if (sz == (long)NSTEPS * BATCH * DIM) dW = p;
    }
    float* out = (float*)d_out;

    static bool attr_set = false;
    const size_t smem_bytes = (size_t)(BPC * MSAMP + 2 * TPB + DIM * BPC) * sizeof(float);
    if (!attr_set) {
        cudaFuncSetAttribute(sde_kernel, cudaFuncAttributeMaxDynamicSharedMemorySize,
                             (int)smem_bytes);
        attr_set = true;
    }

    prep_kernel<<<1, 256>>>(t);
    gt_kernel<<<(DIM * NPAD + 255) / 256, 256>>>(G);
    sde_kernel<<<NGROUP, TPB, smem_bytes>>>(y0, dW, out);
}